// round 3
// baseline (speedup 1.0000x reference)
#include <cuda_runtime.h>
#include <math.h>

#define B_ 8
#define S_ 1024
#define H_ 1024
#define D_ 512
#define N_ 16
#define BS_ (B_*S_)   // 8192
#define DECAYF 0.9f
#define EPS_LN 1e-5f

// ---------------- scratch (static device globals; no allocation) ----------------
__device__ float g_items  [BS_*D_];
__device__ float g_queries[BS_*H_];
__device__ float g_khid   [BS_*H_];
__device__ float g_keys   [BS_*D_];
__device__ float g_bound  [BS_*D_];
__device__ float g_v      [BS_*D_];
__device__ float g_preg1  [BS_*H_];
__device__ float g_preo   [BS_*H_];
__device__ float g_mixed  [BS_*D_];
__device__ float g_ctx    [BS_*D_];

__device__ __forceinline__ float gelu_f(float x) {
    return 0.5f * x * (1.0f + erff(x * 0.70710678118654752f));
}

// ---------------- generic fp32 GEMM: C = act(A@W + bias (+C)) ----------------
// A [M,K] row-major, W [K,N] row-major, C [M,N]. M%128==0, N%128==0, K%16==0.
__global__ __launch_bounds__(256)
void sgemm_kernel(const float* __restrict__ A, const float* __restrict__ W,
                  const float* __restrict__ bias, float* __restrict__ C,
                  int M, int K, int N, int act, int accum)
{
    const int BK = 16;
    __shared__ float As[BK][128];
    __shared__ float Ws[BK][128];
    int tid = threadIdx.x;
    int row0 = blockIdx.y * 128;
    int col0 = blockIdx.x * 128;
    int ty = tid >> 4, tx = tid & 15;

    float acc[8][8];
#pragma unroll
    for (int i = 0; i < 8; i++)
#pragma unroll
        for (int j = 0; j < 8; j++) acc[i][j] = 0.f;

    for (int k0 = 0; k0 < K; k0 += BK) {
#pragma unroll
        for (int q = 0; q < 2; q++) {
            int id = tid * 2 + q;             // 0..511
            int ar = id >> 2;                 // 0..127
            int ac = (id & 3) * 4;            // 0,4,8,12
            float4 av = *(const float4*)(A + (size_t)(row0 + ar) * K + k0 + ac);
            As[ac + 0][ar] = av.x; As[ac + 1][ar] = av.y;
            As[ac + 2][ar] = av.z; As[ac + 3][ar] = av.w;
            int wr = id >> 5;                 // 0..15
            int wc = (id & 31) * 4;           // 0..124
            *(float4*)&Ws[wr][wc] =
                *(const float4*)(W + (size_t)(k0 + wr) * N + col0 + wc);
        }
        __syncthreads();
#pragma unroll
        for (int k = 0; k < BK; k++) {
            float a[8], b[8];
            *(float4*)&a[0] = *(const float4*)&As[k][ty * 8];
            *(float4*)&a[4] = *(const float4*)&As[k][ty * 8 + 4];
            *(float4*)&b[0] = *(const float4*)&Ws[k][tx * 8];
            *(float4*)&b[4] = *(const float4*)&Ws[k][tx * 8 + 4];
#pragma unroll
            for (int i = 0; i < 8; i++)
#pragma unroll
                for (int j = 0; j < 8; j++) acc[i][j] += a[i] * b[j];
        }
        __syncthreads();
    }
#pragma unroll
    for (int i = 0; i < 8; i++) {
        int r = row0 + ty * 8 + i;
#pragma unroll
        for (int j = 0; j < 8; j += 4) {
            int c = col0 + tx * 8 + j;
            float4 o = make_float4(acc[i][j], acc[i][j+1], acc[i][j+2], acc[i][j+3]);
            if (bias) {
                o.x += bias[c]; o.y += bias[c+1]; o.z += bias[c+2]; o.w += bias[c+3];
            }
            if (accum) {
                float4 p = *(const float4*)(C + (size_t)r * N + c);
                o.x += p.x; o.y += p.y; o.z += p.z; o.w += p.w;
            }
            if (act == 1) {
                o.x = gelu_f(o.x); o.y = gelu_f(o.y); o.z = gelu_f(o.z); o.w = gelu_f(o.w);
            }
            *(float4*)(C + (size_t)r * N + c) = o;
        }
    }
}

// ---------------- batched circular conv/corr over D=512 ----------------
// sign=1: out[d] = sum_m Bv[m] * A[(d-m)&511]   (circular convolution)
// sign=0: out[d] = sum_m Bv[m] * A[(m-d)&511]   (circular correlation form)
// bmode: 0 = B shared; 1 = B row = blk%1024; 2 = B row = blk
__global__ __launch_bounds__(512)
void circ_kernel(const float* __restrict__ A, const float* __restrict__ Bsrc,
                 float* __restrict__ out, int bmode, int sign)
{
    __shared__ float Adup[1024];
    __shared__ float Bv[512];
    int blk = blockIdx.x, tid = threadIdx.x;
    const float* Arow = A + (size_t)blk * 512;
    const float* Brow = (bmode == 0) ? Bsrc
                      : (bmode == 1) ? (Bsrc + (size_t)(blk & 1023) * 512)
                                     : (Bsrc + (size_t)blk * 512);
    float a = Arow[tid];
    Adup[tid] = a; Adup[tid + 512] = a;
    Bv[tid] = Brow[tid];
    __syncthreads();
    float acc = 0.f;
    if (sign) {
        int base = tid + 512;
#pragma unroll 8
        for (int m = 0; m < 512; m++) acc += Bv[m] * Adup[base - m];
    } else {
        int base = 512 - tid;
#pragma unroll 8
        for (int m = 0; m < 512; m++) acc += Bv[m] * Adup[base + m];
    }
    out[(size_t)blk * 512 + tid] = acc;
}

// ---------------- row L2-normalize (keys), rows of 512 ----------------
__global__ __launch_bounds__(128)
void rownorm_kernel(float* __restrict__ keys)
{
    int row = blockIdx.x, tid = threadIdx.x;
    __shared__ float rs[4];
    float4 v = *(float4*)(keys + (size_t)row * 512 + tid * 4);
    float ss = v.x*v.x + v.y*v.y + v.z*v.z + v.w*v.w;
#pragma unroll
    for (int off = 16; off; off >>= 1) ss += __shfl_xor_sync(0xffffffffu, ss, off);
    int w = tid >> 5, l = tid & 31;
    if (l == 0) rs[w] = ss;
    __syncthreads();
    ss = rs[0] + rs[1] + rs[2] + rs[3];
    float inv = 1.f / fmaxf(sqrtf(ss), 1e-12f);
    v.x *= inv; v.y *= inv; v.z *= inv; v.w *= inv;
    *(float4*)(keys + (size_t)row * 512 + tid * 4) = v;
}

// ---------------- phase 2: sequential scan (one block per batch) ----------------
// Static smem only (~41 KB). Gating weights live in registers:
//   thread tid: wg1a[n] = Wg1[1536+n][tid], wg1b[n] = Wg1[1536+n][tid+512]
//   lane l of warp w: wg2r[i] = Wg2[l+32*i][w]
__global__ __launch_bounds__(512)
void phase2_kernel(const float* __restrict__ v_g, const float* __restrict__ bound_g,
                   const float* __restrict__ preg1_g, const float* __restrict__ Wg1,
                   const float* __restrict__ Wg2, const float* __restrict__ bg2,
                   const float* __restrict__ bsa, float* __restrict__ mixed_g,
                   float* __restrict__ hcm_out)
{
    __shared__ float hcm_s[8192];
    __shared__ float g_s[1024];
    __shared__ float v_s[512];
    __shared__ float bnd_s[512];
    __shared__ float scores_s[16], stats_s[16], wts_s[16], gates_s[16], bg2_s[16];

    int b = blockIdx.x;
    int tid = threadIdx.x;             // 512 threads = 16 warps
    int w = tid >> 5, l = tid & 31;

    float wg1a[16], wg1b[16], wg2r[32];
#pragma unroll
    for (int n = 0; n < 16; ++n) {
        wg1a[n] = Wg1[(size_t)(1536 + n) * 1024 + tid];
        wg1b[n] = Wg1[(size_t)(1536 + n) * 1024 + tid + 512];
    }
#pragma unroll
    for (int i = 0; i < 32; ++i)
        wg2r[i] = Wg2[(size_t)(l + 32 * i) * 16 + w];

    for (int i = tid; i < 8192; i += 512) hcm_s[i] = 0.f;
    if (tid < 16) bg2_s[tid] = bg2[tid];
    float bsa0 = bsa[0];

    size_t rbase = (size_t)b * S_;
    float v_pf  = v_g[rbase * 512 + tid];
    float b_pf  = bound_g[rbase * 512 + tid];
    float pg0_pf = preg1_g[rbase * 1024 + tid];
    float pg1_pf = preg1_g[rbase * 1024 + tid + 512];
    __syncthreads();

    for (int t = 0; t < S_; ++t) {
        v_s[tid] = v_pf;  bnd_s[tid] = b_pf;
        float pg0 = pg0_pf, pg1 = pg1_pf;
        __syncthreads();                                  // B1
        if (t + 1 < S_) {
            size_t rb = rbase + t + 1;
            v_pf  = v_g[rb * 512 + tid];
            b_pf  = bound_g[rb * 512 + tid];
            pg0_pf = preg1_g[rb * 1024 + tid];
            pg1_pf = preg1_g[rb * 1024 + tid + 512];
        }
        // scores + stats: warp w owns slot w
        float dv = 0.f, dh = 0.f;
#pragma unroll
        for (int i = 0; i < 16; ++i) {
            float hv = hcm_s[w * 512 + l + i * 32];
            dv += hv * v_s[l + i * 32];
            dh += hv * hv;
        }
#pragma unroll
        for (int off = 16; off; off >>= 1) {
            dv += __shfl_xor_sync(0xffffffffu, dv, off);
            dh += __shfl_xor_sync(0xffffffffu, dh, off);
        }
        if (l == 0) { scores_s[w] = dv + bsa0; stats_s[w] = sqrtf(dh); }
        __syncthreads();                                  // B2
        // softmax over N=16 (warp 0)
        if (tid < 32) {
            float sc = (l < 16) ? scores_s[l] : -3.4e38f;
            float mx = sc;
#pragma unroll
            for (int off = 16; off; off >>= 1)
                mx = fmaxf(mx, __shfl_xor_sync(0xffffffffu, mx, off));
            float e = (l < 16) ? expf(sc - mx) : 0.f;
            float su = e;
#pragma unroll
            for (int off = 16; off; off >>= 1)
                su += __shfl_xor_sync(0xffffffffu, su, off);
            if (l < 16) wts_s[l] = e / su;
        }
        // gating hidden layer (uses stats_s; weights in registers)
        {
            float a0 = pg0, a1 = pg1;
#pragma unroll
            for (int n = 0; n < 16; ++n) {
                float st = stats_s[n];
                a0 += st * wg1a[n];
                a1 += st * wg1b[n];
            }
            g_s[tid] = gelu_f(a0);
            g_s[tid + 512] = gelu_f(a1);
        }
        __syncthreads();                                  // B3
        // gates (warp w owns slot w; Wg2 column w in registers)
        float ga = 0.f;
#pragma unroll
        for (int i = 0; i < 32; ++i)
            ga += g_s[l + i * 32] * wg2r[i];
#pragma unroll
        for (int off = 16; off; off >>= 1)
            ga += __shfl_xor_sync(0xffffffffu, ga, off);
        if (l == 0) gates_s[w] = 1.f / (1.f + expf(-(ga + bg2_s[w])));
        // mixed = sum_n wts[n] * hcm[n, d]
        float mx = 0.f;
#pragma unroll
        for (int n = 0; n < 16; ++n) mx += wts_s[n] * hcm_s[n * 512 + tid];
        mixed_g[(rbase + t) * 512 + tid] = mx;
        __syncthreads();                                  // B4
        // memory update
        float bv = bnd_s[tid];
#pragma unroll
        for (int n = 0; n < 16; ++n)
            hcm_s[n * 512 + tid] = DECAYF * hcm_s[n * 512 + tid] + gates_s[n] * bv;
    }
    __syncthreads();
    for (int i = tid; i < 8192; i += 512)
        hcm_out[(size_t)b * 8192 + i] = hcm_s[i];
}

// ---------------- residual + layernorm ----------------
__global__ __launch_bounds__(256)
void ln_kernel(const float* __restrict__ hs, const float* __restrict__ preo,
               const float* __restrict__ lng, const float* __restrict__ lnb,
               float* __restrict__ out)
{
    int row = blockIdx.x, tid = threadIdx.x;
    __shared__ float rs[8], rs2[8];
    size_t base = (size_t)row * 1024;
    float v[4]; float s = 0.f, s2 = 0.f;
#pragma unroll
    for (int i = 0; i < 4; i++) {
        int h = tid + i * 256;
        float x = hs[base + h] + preo[base + h];
        v[i] = x; s += x; s2 += x * x;
    }
#pragma unroll
    for (int off = 16; off; off >>= 1) {
        s  += __shfl_xor_sync(0xffffffffu, s, off);
        s2 += __shfl_xor_sync(0xffffffffu, s2, off);
    }
    int w = tid >> 5, l = tid & 31;
    if (l == 0) { rs[w] = s; rs2[w] = s2; }
    __syncthreads();
    s = 0.f; s2 = 0.f;
#pragma unroll
    for (int i = 0; i < 8; i++) { s += rs[i]; s2 += rs2[i]; }
    float mu = s * (1.f / 1024.f);
    float var = s2 * (1.f / 1024.f) - mu * mu;
    float rstd = rsqrtf(var + EPS_LN);
#pragma unroll
    for (int i = 0; i < 4; i++) {
        int h = tid + i * 256;
        out[base + h] = (v[i] - mu) * rstd * lng[h] + lnb[h];
    }
}

// ---------------- host launcher ----------------
extern "C" void kernel_launch(void* const* d_in, const int* in_sizes, int n_in,
                              void* d_out, int out_size)
{
    const float* hs  = (const float*)d_in[0];
    const float* pos = (const float*)d_in[1];
    const float* Wi  = (const float*)d_in[2];
    const float* bi  = (const float*)d_in[3];
    const float* Wq  = (const float*)d_in[4];
    const float* bq  = (const float*)d_in[5];
    const float* Wk1 = (const float*)d_in[6];
    const float* bk1 = (const float*)d_in[7];
    const float* Wk2 = (const float*)d_in[8];
    const float* bk2 = (const float*)d_in[9];
    const float* Wsa = (const float*)d_in[10];
    const float* bsa = (const float*)d_in[11];
    const float* Wg1 = (const float*)d_in[12];
    const float* bg1 = (const float*)d_in[13];
    const float* Wg2 = (const float*)d_in[14];
    const float* bg2 = (const float*)d_in[15];
    const float* Wo  = (const float*)d_in[16];
    const float* bo  = (const float*)d_in[17];
    const float* lng = (const float*)d_in[18];
    const float* lnb = (const float*)d_in[19];
    float* out = (float*)d_out;

    float *items, *queries, *khid, *keys, *bound, *v, *preg1, *preo, *mixed, *ctx;
    cudaGetSymbolAddress((void**)&items,   g_items);
    cudaGetSymbolAddress((void**)&queries, g_queries);
    cudaGetSymbolAddress((void**)&khid,    g_khid);
    cudaGetSymbolAddress((void**)&keys,    g_keys);
    cudaGetSymbolAddress((void**)&bound,   g_bound);
    cudaGetSymbolAddress((void**)&v,       g_v);
    cudaGetSymbolAddress((void**)&preg1,   g_preg1);
    cudaGetSymbolAddress((void**)&preo,    g_preo);
    cudaGetSymbolAddress((void**)&mixed,   g_mixed);
    cudaGetSymbolAddress((void**)&ctx,     g_ctx);

    dim3 gN(H_ / 128, BS_ / 128);   // N=1024 GEMMs
    dim3 gD(D_ / 128, BS_ / 128);   // N=512 GEMMs

    // Phase 1: parallel precompute
    sgemm_kernel<<<gN, 256>>>(hs, Wq, bq, queries, BS_, H_, H_, 0, 0);
    sgemm_kernel<<<gD, 256>>>(hs, Wi, bi, items,   BS_, H_, D_, 0, 0);
    sgemm_kernel<<<gN, 256>>>(queries, Wk1, bk1, khid, BS_, H_, H_, 1, 0);      // gelu
    sgemm_kernel<<<gD, 256>>>(khid, Wk2, bk2, keys, BS_, H_, D_, 0, 0);
    rownorm_kernel<<<BS_, 128>>>(keys);
    circ_kernel<<<BS_, 512>>>(items, pos, bound, 1, 1);   // bound = conv(items, pos_s)
    circ_kernel<<<BS_, 512>>>(keys, Wsa, v, 0, 1);        // v = conv(keys, Wsa)
    sgemm_kernel<<<gN, 256>>>(queries, Wg1, bg1, preg1, BS_, H_, H_, 0, 0);
    sgemm_kernel<<<gN, 256>>>(items, Wg1 + (size_t)H_ * H_, nullptr, preg1,
                              BS_, D_, H_, 0, 1);         // += items @ Wg1[H:H+D]
    sgemm_kernel<<<gN, 256>>>(queries, Wo, bo, preo, BS_, H_, H_, 0, 0);

    // Phase 2: sequential scan, one block per batch element
    phase2_kernel<<<B_, 512>>>(v, bound, preg1, Wg1, Wg2, bg2, bsa,
                               mixed, out + (size_t)BS_ * H_);

    // Phase 3: deferred retrieval + output projection + LN
    circ_kernel<<<BS_, 512>>>(keys, mixed, ctx, 2, 0);    // ctx = corr(mixed, keys)
    sgemm_kernel<<<gN, 256>>>(ctx, Wo + (size_t)H_ * H_, nullptr, preo,
                              BS_, D_, H_, 0, 1);         // += ctx @ Wo[H:H+D]
    ln_kernel<<<BS_, 256>>>(hs, preo, lng, lnb, out);
}